// round 7
// baseline (speedup 1.0000x reference)
#include <cuda_runtime.h>
#include <cstdint>

#define KTAG 64
#define BTOT 1024
#define TLEN 512
#define START_TAG 62

#define FWD_BLOCKS 128   // 4 warps x 2 rows = 8 rows per block
#define GOLD_BLOCKS 256  // 4 warps x 1 row  = 4 rows per block

// Scratch (allocation-free rule: __device__ globals)
__device__ float g_forward[BTOT];
__device__ float g_gold[BTOT];

typedef unsigned long long ull;

__device__ __forceinline__ ull pk2(float x, float y) {
    return (ull)__float_as_uint(x) | ((ull)__float_as_uint(y) << 32);
}
__device__ __forceinline__ float lo2(ull v) { return __uint_as_float((unsigned)v); }
__device__ __forceinline__ float hi2(ull v) { return __uint_as_float((unsigned)(v >> 32)); }
__device__ __forceinline__ float rcpf(float x) {
    float r; asm("rcp.approx.f32 %0, %1;" : "=f"(r) : "f"(x)); return r;
}

#define FMA2(acc, a, b) asm("fma.rn.f32x2 %0, %1, %2, %0;" : "+l"(acc) : "l"(a), "l"(b))
#define ADD2(d, a, b)   asm("add.rn.f32x2 %0, %1, %2;" : "=l"(d) : "l"(a), "l"(b))
#define MUL2(d, a, b)   asm("mul.rn.f32x2 %0, %1, %2;" : "=l"(d) : "l"(a), "l"(b))

// ---------------------------------------------------------------------------
// Merged kernel.
// Blocks [0, FWD_BLOCKS): forward recurrence. One warp handles TWO batch rows
//   (A, B) interleaved — E (exp(transitions), 128 regs) is shared between the
//   rows, and the two independent dependency chains fill each other's stall
//   gaps. Each row keeps the R6 scheme: deferred normalization (u = w[0]),
//   4-deep feat prefetch pipeline (MLP=4 per row), 16 LDS.128 + 64 FMA2 per
//   row-step, no cross-warp sync.
// Blocks [FWD_BLOCKS, FWD_BLOCKS+GOLD_BLOCKS): gold-path score, one warp per
//   batch row (lanes stride t). Overlaps with forward in the same launch.
// ---------------------------------------------------------------------------
__global__ void __launch_bounds__(128, 1)
crf_main_kernel(const float* __restrict__ feats,
                const int* __restrict__ tags,
                const float* __restrict__ trans) {
    const int lane = threadIdx.x & 31;
    const int w    = threadIdx.x >> 5;          // warp within CTA (0..3)

    if (blockIdx.x >= FWD_BLOCKS) {
        // ----------------- gold-path score -----------------
        const int b = (blockIdx.x - FWD_BLOCKS) * 4 + w;
        const int*   tg  = tags  + (size_t)b * TLEN;
        const float* fbp = feats + (size_t)b * TLEN * KTAG;
        float s = 0.0f;
        for (int t = 1 + lane; t < TLEN; t += 32) {
            int ct = tg[t];
            int pt = tg[t - 1];
            s += trans[ct * KTAG + pt] + fbp[(size_t)t * KTAG + ct];
        }
#pragma unroll
        for (int o = 16; o > 0; o >>= 1)
            s += __shfl_xor_sync(0xffffffffu, s, o);
        if (lane == 0) g_gold[b] = s;
        return;
    }

    // ----------------- forward recurrence, 2 rows per warp -----------------
    const int bA = blockIdx.x * 8 + w * 2;      // row A
    const int bB = bA + 1;                      // row B
    const int i0 = 2 * lane;
    const int i1 = 2 * lane + 1;

    __shared__ __align__(16) float sw_[4][2][2][KTAG];  // [warp][row][buf][tag]

    // E rows for tags i0, i1 (f32x2 packed over j) — shared by both batch rows
    ull E0[32], E1[32];
#pragma unroll
    for (int jj = 0; jj < 32; jj++) {
        E0[jj] = pk2(__expf(trans[i0 * KTAG + 2 * jj]),
                     __expf(trans[i0 * KTAG + 2 * jj + 1]));
        E1[jj] = pk2(__expf(trans[i1 * KTAG + 2 * jj]),
                     __expf(trans[i1 * KTAG + 2 * jj + 1]));
    }

    const float* fbA = feats + (size_t)bA * TLEN * KTAG;
    const float* fbB = feats + (size_t)bB * TLEN * KTAG;

    // t = 1 exact for both rows
    {
        float2 f1A = *(const float2*)(fbA + 1 * KTAG + i0);
        float2 f1B = *(const float2*)(fbB + 1 * KTAG + i0);
        float tA0 = trans[i0 * KTAG + START_TAG];
        float tA1 = trans[i1 * KTAG + START_TAG];
        *(float2*)&sw_[w][0][0][i0] =
            make_float2(__expf(tA0 + f1A.x), __expf(tA1 + f1A.y));
        *(float2*)&sw_[w][1][0][i0] =
            make_float2(__expf(tA0 + f1B.x), __expf(tA1 + f1B.y));
    }
    float LA = 0.0f, LB = 0.0f;

    // 4-deep feat pipelines per row
    float2 FA[4], FB[4];
#pragma unroll
    for (int k = 0; k < 4; k++) {
        FA[k] = *(const float2*)(fbA + (size_t)(2 + k) * KTAG + i0);
        FB[k] = *(const float2*)(fbB + (size_t)(2 + k) * KTAG + i0);
    }
    __syncwarp();

    // one recurrence step for BOTH rows, interleaved
#define STEP2(T, eA0, eA1, eB0, eB1)                                          \
    {                                                                         \
        const int rbuf = (T) & 1;                                             \
        const ulonglong2* vpA = (const ulonglong2*)sw_[w][0][rbuf];           \
        const ulonglong2* vpB = (const ulonglong2*)sw_[w][1][rbuf];           \
        ulonglong2 vA0 = vpA[0];                                              \
        ulonglong2 vB0 = vpB[0];                                              \
        float uuA = lo2(vA0.x), uuB = lo2(vB0.x);                             \
        float rA = rcpf(uuA), rB = rcpf(uuB);                                 \
        LA += __logf(uuA);                                                    \
        LB += __logf(uuB);                                                    \
        ull a0 = 0, a1 = 0, a2 = 0, a3 = 0, a4 = 0, a5 = 0, a6 = 0, a7 = 0;   \
        ull b0 = 0, b1 = 0, b2 = 0, b3 = 0, b4 = 0, b5 = 0, b6 = 0, b7 = 0;   \
        FMA2(a0, E0[0], vA0.x); FMA2(a1, E0[1], vA0.y);                       \
        FMA2(a2, E1[0], vA0.x); FMA2(a3, E1[1], vA0.y);                       \
        FMA2(b0, E0[0], vB0.x); FMA2(b1, E0[1], vB0.y);                       \
        FMA2(b2, E1[0], vB0.x); FMA2(b3, E1[1], vB0.y);                       \
        _Pragma("unroll")                                                     \
        for (int q = 1; q < 16; q++) {                                        \
            ulonglong2 vvA = vpA[q];                                          \
            ulonglong2 vvB = vpB[q];                                          \
            if (q & 1) {                                                      \
                FMA2(a4, E0[2 * q], vvA.x); FMA2(a5, E0[2 * q + 1], vvA.y);   \
                FMA2(a6, E1[2 * q], vvA.x); FMA2(a7, E1[2 * q + 1], vvA.y);   \
                FMA2(b4, E0[2 * q], vvB.x); FMA2(b5, E0[2 * q + 1], vvB.y);   \
                FMA2(b6, E1[2 * q], vvB.x); FMA2(b7, E1[2 * q + 1], vvB.y);   \
            } else {                                                          \
                FMA2(a0, E0[2 * q], vvA.x); FMA2(a1, E0[2 * q + 1], vvA.y);   \
                FMA2(a2, E1[2 * q], vvA.x); FMA2(a3, E1[2 * q + 1], vvA.y);   \
                FMA2(b0, E0[2 * q], vvB.x); FMA2(b1, E0[2 * q + 1], vvB.y);   \
                FMA2(b2, E1[2 * q], vvB.x); FMA2(b3, E1[2 * q + 1], vvB.y);   \
            }                                                                 \
        }                                                                     \
        ull tmp0, tmp1, csA, dsA, csB, dsB, wnA, wnB;                         \
        ADD2(tmp0, a0, a4); ADD2(tmp1, a1, a5); ADD2(csA, tmp0, tmp1);        \
        ADD2(tmp0, a2, a6); ADD2(tmp1, a3, a7); ADD2(dsA, tmp0, tmp1);        \
        ADD2(tmp0, b0, b4); ADD2(tmp1, b1, b5); ADD2(csB, tmp0, tmp1);        \
        ADD2(tmp0, b2, b6); ADD2(tmp1, b3, b7); ADD2(dsB, tmp0, tmp1);        \
        float sA0 = lo2(csA) + hi2(csA);                                      \
        float sA1 = lo2(dsA) + hi2(dsA);                                      \
        float sB0 = lo2(csB) + hi2(csB);                                      \
        float sB1 = lo2(dsB) + hi2(dsB);                                      \
        MUL2(wnA, pk2(sA0, sA1), pk2((eA0) * rA, (eA1) * rA));                \
        MUL2(wnB, pk2(sB0, sB1), pk2((eB0) * rB, (eB1) * rB));                \
        *(ull*)&sw_[w][0][rbuf ^ 1][i0] = wnA;                                \
        *(ull*)&sw_[w][1][rbuf ^ 1][i0] = wnB;                                \
        __syncwarp();                                                         \
    }

    // main loop: t = 2 .. 509, 127 blocks of 4 (MLP=4 per row, 8 LDGs in flight)
    for (int kb = 0; kb < 127; kb++) {
#pragma unroll
        for (int k = 0; k < 4; k++) {
            const int t = 2 + 4 * kb + k;
            float eA0 = __expf(FA[k].x), eA1 = __expf(FA[k].y);
            float eB0 = __expf(FB[k].x), eB1 = __expf(FB[k].y);
            int tn = t + 4; if (tn > TLEN - 1) tn = TLEN - 1;
            FA[k] = *(const float2*)(fbA + (size_t)tn * KTAG + i0);
            FB[k] = *(const float2*)(fbB + (size_t)tn * KTAG + i0);
            STEP2(t, eA0, eA1, eB0, eB1)
        }
    }

    // t = 510 (feats in FA[0]/FB[0])
    {
        float eA0 = __expf(FA[0].x), eA1 = __expf(FA[0].y);
        float eB0 = __expf(FB[0].x), eB1 = __expf(FB[0].y);
        STEP2(510, eA0, eA1, eB0, eB1)
    }

    // final step t = 511 (feats in FA[1]/FB[1])
    {
        float eA0 = __expf(FA[1].x), eA1 = __expf(FA[1].y);
        float eB0 = __expf(FB[1].x), eB1 = __expf(FB[1].y);
        const int rbuf = (TLEN - 1) & 1;
        const ulonglong2* vpA = (const ulonglong2*)sw_[w][0][rbuf];
        const ulonglong2* vpB = (const ulonglong2*)sw_[w][1][rbuf];
        ull a0 = 0, a1 = 0, a2 = 0, a3 = 0, a4 = 0, a5 = 0, a6 = 0, a7 = 0;
        ull b0 = 0, b1 = 0, b2 = 0, b3 = 0, b4 = 0, b5 = 0, b6 = 0, b7 = 0;
#pragma unroll
        for (int q = 0; q < 16; q++) {
            ulonglong2 vvA = vpA[q];
            ulonglong2 vvB = vpB[q];
            if (q & 1) {
                FMA2(a4, E0[2 * q], vvA.x); FMA2(a5, E0[2 * q + 1], vvA.y);
                FMA2(a6, E1[2 * q], vvA.x); FMA2(a7, E1[2 * q + 1], vvA.y);
                FMA2(b4, E0[2 * q], vvB.x); FMA2(b5, E0[2 * q + 1], vvB.y);
                FMA2(b6, E1[2 * q], vvB.x); FMA2(b7, E1[2 * q + 1], vvB.y);
            } else {
                FMA2(a0, E0[2 * q], vvA.x); FMA2(a1, E0[2 * q + 1], vvA.y);
                FMA2(a2, E1[2 * q], vvA.x); FMA2(a3, E1[2 * q + 1], vvA.y);
                FMA2(b0, E0[2 * q], vvB.x); FMA2(b1, E0[2 * q + 1], vvB.y);
                FMA2(b2, E1[2 * q], vvB.x); FMA2(b3, E1[2 * q + 1], vvB.y);
            }
        }
        ull tmp0, tmp1, csA, dsA, csB, dsB;
        ADD2(tmp0, a0, a4); ADD2(tmp1, a1, a5); ADD2(csA, tmp0, tmp1);
        ADD2(tmp0, a2, a6); ADD2(tmp1, a3, a7); ADD2(dsA, tmp0, tmp1);
        ADD2(tmp0, b0, b4); ADD2(tmp1, b1, b5); ADD2(csB, tmp0, tmp1);
        ADD2(tmp0, b2, b6); ADD2(tmp1, b3, b7); ADD2(dsB, tmp0, tmp1);
        float zA = (lo2(csA) + hi2(csA)) * eA0 + (lo2(dsA) + hi2(dsA)) * eA1;
        float zB = (lo2(csB) + hi2(csB)) * eB0 + (lo2(dsB) + hi2(dsB)) * eB1;
#pragma unroll
        for (int o = 16; o > 0; o >>= 1) {
            zA += __shfl_xor_sync(0xffffffffu, zA, o);
            zB += __shfl_xor_sync(0xffffffffu, zB, o);
        }
        if (lane == 0) {
            g_forward[bA] = LA + __logf(zA);
            g_forward[bB] = LB + __logf(zB);
        }
    }
#undef STEP2
}

// ---------------------------------------------------------------------------
// Final deterministic reduction: mean(forward - gold) over B.
// ---------------------------------------------------------------------------
__global__ void __launch_bounds__(256)
crf_reduce_kernel(float* __restrict__ out) {
    __shared__ float sh[8];
    int tid  = threadIdx.x;
    int warp = tid >> 5;
    int lane = tid & 31;

    float s = 0.0f;
    for (int x = tid; x < BTOT; x += 256)
        s += g_forward[x] - g_gold[x];
#pragma unroll
    for (int o = 16; o > 0; o >>= 1)
        s += __shfl_xor_sync(0xffffffffu, s, o);
    if (lane == 0) sh[warp] = s;
    __syncthreads();
    if (tid == 0) {
        float tot = 0.0f;
#pragma unroll
        for (int w = 0; w < 8; w++) tot += sh[w];
        out[0] = tot / (float)BTOT;
    }
}

extern "C" void kernel_launch(void* const* d_in, const int* in_sizes, int n_in,
                              void* d_out, int out_size) {
    const float* feats = (const float*)d_in[0];
    const int*   tags  = (const int*)d_in[1];
    const float* trans = (const float*)d_in[2];
    float* out = (float*)d_out;

    crf_main_kernel<<<FWD_BLOCKS + GOLD_BLOCKS, 128>>>(feats, tags, trans);
    crf_reduce_kernel<<<1, 256>>>(out);
}

// round 8
// speedup vs baseline: 1.6560x; 1.6560x over previous
#include <cuda_runtime.h>
#include <cstdint>

#define KTAG 64
#define BTOT 1024
#define TLEN 512
#define START_TAG 62

#define GOLD_GRID 512   // 8 warps/block, 4 T-segments per row

// Scratch (allocation-free rule: __device__ globals)
__device__ float g_forward[BTOT];
__device__ float g_goldp[BTOT * 4];
__device__ int   g_cnt = 0;

typedef unsigned long long ull;

__device__ __forceinline__ ull pk2(float x, float y) {
    return (ull)__float_as_uint(x) | ((ull)__float_as_uint(y) << 32);
}
__device__ __forceinline__ float lo2(ull v) { return __uint_as_float((unsigned)v); }
__device__ __forceinline__ float hi2(ull v) { return __uint_as_float((unsigned)(v >> 32)); }
__device__ __forceinline__ float rcpf(float x) {
    float r; asm("rcp.approx.f32 %0, %1;" : "=f"(r) : "f"(x)); return r;
}

#define FMA2(acc, a, b) asm("fma.rn.f32x2 %0, %1, %2, %0;" : "+l"(acc) : "l"(a), "l"(b))
#define ADD2(d, a, b)   asm("add.rn.f32x2 %0, %1, %2;" : "=l"(d) : "l"(a), "l"(b))
#define MUL2(d, a, b)   asm("mul.rn.f32x2 %0, %1, %2;" : "=l"(d) : "l"(a), "l"(b))

// ---------------------------------------------------------------------------
// Forward kernel (R6 structure): 1 warp per batch row, 2 tags per lane,
// E = exp(transitions) in 128 regs, deferred normalization (u = w[0]),
// 4-deep feat prefetch pipeline (MLP=4).
// NEW: CTAs with blockIdx.x >= 148 (the second co-resident CTA on each SM)
// delay ~320 cycles before the main loop to de-phase the two warps sharing
// each SMSP, so one warp's FMA burst overlaps the other's serial tail.
// ---------------------------------------------------------------------------
__global__ void __launch_bounds__(128, 2)
crf_forward_kernel(const float* __restrict__ feats,
                   const float* __restrict__ trans) {
    const int lane = threadIdx.x & 31;
    const int w    = threadIdx.x >> 5;          // row within CTA (0..3)
    const int b    = blockIdx.x * 4 + w;
    const int i0   = 2 * lane;
    const int i1   = 2 * lane + 1;

    __shared__ __align__(16) float sw_[4][2][KTAG];

    // E rows for tags i0, i1 (f32x2 packed over j)
    ull E0[32], E1[32];
#pragma unroll
    for (int jj = 0; jj < 32; jj++) {
        E0[jj] = pk2(__expf(trans[i0 * KTAG + 2 * jj]),
                     __expf(trans[i0 * KTAG + 2 * jj + 1]));
        E1[jj] = pk2(__expf(trans[i1 * KTAG + 2 * jj]),
                     __expf(trans[i1 * KTAG + 2 * jj + 1]));
    }

    const float* fb = feats + (size_t)b * TLEN * KTAG;

    // t = 1 exact: alpha1[i] = trans[i, START] + feat1[i]; w1 = exp(alpha1)
    float2 f1 = *(const float2*)(fb + 1 * KTAG + i0);
    float a0 = trans[i0 * KTAG + START_TAG] + f1.x;
    float a1 = trans[i1 * KTAG + START_TAG] + f1.y;
    *(float2*)&sw_[w][0][i0] = make_float2(__expf(a0), __expf(a1));
    float L = 0.0f;

    // 4-deep feat pipeline: F[k] = feat(t = 2+k)
    float2 F[4];
#pragma unroll
    for (int k = 0; k < 4; k++)
        F[k] = *(const float2*)(fb + (size_t)(2 + k) * KTAG + i0);
    __syncwarp();

    // de-phase: second-layer CTAs wait ~320 cyc (80 dependent FFMAs)
    if (blockIdx.x >= 148) {
        float d = trans[lane];  // runtime value, not foldable
#pragma unroll
        for (int k = 0; k < 80; k++)
            asm volatile("fma.rn.f32 %0, %0, %0, %1;" : "+f"(d) : "f"(1.0f));
        if (d == 123456789.0f) sw_[w][0][i0] = d;  // never true; keeps chain
    }

    // one recurrence step; efc0/efc1 = exp(feat_t) for this step
#define STEP_BODY(T, EFC0, EFC1)                                              \
    {                                                                         \
        const int rbuf = (T) & 1;                                             \
        const ulonglong2* vp = (const ulonglong2*)sw_[w][rbuf];               \
        ulonglong2 v0 = vp[0];                                                \
        float uu = lo2(v0.x);                                                 \
        float r  = rcpf(uu);                                                  \
        L += __logf(uu);                                                      \
        ull c0 = 0, c1 = 0, c2 = 0, c3 = 0;                                   \
        ull d0 = 0, d1 = 0, d2 = 0, d3 = 0;                                   \
        FMA2(c0, E0[0], v0.x); FMA2(c1, E0[1], v0.y);                         \
        FMA2(d0, E1[0], v0.x); FMA2(d1, E1[1], v0.y);                         \
        _Pragma("unroll")                                                     \
        for (int q = 1; q < 16; q++) {                                        \
            ulonglong2 vv = vp[q];                                            \
            if (q & 1) {                                                      \
                FMA2(c2, E0[2 * q], vv.x); FMA2(c3, E0[2 * q + 1], vv.y);     \
                FMA2(d2, E1[2 * q], vv.x); FMA2(d3, E1[2 * q + 1], vv.y);     \
            } else {                                                          \
                FMA2(c0, E0[2 * q], vv.x); FMA2(c1, E0[2 * q + 1], vv.y);     \
                FMA2(d0, E1[2 * q], vv.x); FMA2(d1, E1[2 * q + 1], vv.y);     \
            }                                                                 \
        }                                                                     \
        ull cA, cB, cs, dA, dB, ds, wn, rn;                                   \
        ADD2(cA, c0, c2); ADD2(cB, c1, c3); ADD2(cs, cA, cB);                 \
        ADD2(dA, d0, d2); ADD2(dB, d1, d3); ADD2(ds, dA, dB);                 \
        float s0 = lo2(cs) + hi2(cs);                                         \
        float s1 = lo2(ds) + hi2(ds);                                         \
        rn = pk2((EFC0) * r, (EFC1) * r);                                     \
        MUL2(wn, pk2(s0, s1), rn);                                            \
        *(ull*)&sw_[w][rbuf ^ 1][i0] = wn;                                    \
        __syncwarp();                                                         \
    }

    // main loop: t = 2 .. 509, 127 blocks of 4 (keeps 4 LDGs in flight)
    for (int kb = 0; kb < 127; kb++) {
#pragma unroll
        for (int k = 0; k < 4; k++) {
            const int t = 2 + 4 * kb + k;
            float efc0 = __expf(F[k].x);
            float efc1 = __expf(F[k].y);
            int tn = t + 4; if (tn > TLEN - 1) tn = TLEN - 1;
            F[k] = *(const float2*)(fb + (size_t)tn * KTAG + i0);
            STEP_BODY(t, efc0, efc1)
        }
    }

    // t = 510 (feat in F[0])
    {
        float efc0 = __expf(F[0].x);
        float efc1 = __expf(F[0].y);
        STEP_BODY(510, efc0, efc1)
    }

    // final step t = 511 (feat in F[1]): forward = L + log(sum_i s_i*exp(f_i))
    {
        float ef0 = __expf(F[1].x);
        float ef1 = __expf(F[1].y);
        const int rbuf = (TLEN - 1) & 1;
        const ulonglong2* vp = (const ulonglong2*)sw_[w][rbuf];
        ull c0 = 0, c1 = 0, c2 = 0, c3 = 0;
        ull d0 = 0, d1 = 0, d2 = 0, d3 = 0;
#pragma unroll
        for (int q = 0; q < 16; q++) {
            ulonglong2 vv = vp[q];
            if (q & 1) {
                FMA2(c2, E0[2 * q], vv.x); FMA2(c3, E0[2 * q + 1], vv.y);
                FMA2(d2, E1[2 * q], vv.x); FMA2(d3, E1[2 * q + 1], vv.y);
            } else {
                FMA2(c0, E0[2 * q], vv.x); FMA2(c1, E0[2 * q + 1], vv.y);
                FMA2(d0, E1[2 * q], vv.x); FMA2(d1, E1[2 * q + 1], vv.y);
            }
        }
        ull cA, cB, cs, dA, dB, ds;
        ADD2(cA, c0, c2); ADD2(cB, c1, c3); ADD2(cs, cA, cB);
        ADD2(dA, d0, d2); ADD2(dB, d1, d3); ADD2(ds, dA, dB);
        float s0 = lo2(cs) + hi2(cs);
        float s1 = lo2(ds) + hi2(ds);
        float z = s0 * ef0 + s1 * ef1;
#pragma unroll
        for (int o = 16; o > 0; o >>= 1)
            z += __shfl_xor_sync(0xffffffffu, z, o);
        if (lane == 0) g_forward[b] = L + __logf(z);
    }
#undef STEP_BODY
}

// ---------------------------------------------------------------------------
// Gold-path score + fused final reduction (last-block pattern).
// 4 T-segments per batch row, deterministic partials; the last block to
// finish computes mean(forward - gold) with a fixed summation order and
// resets the counter for graph replay.
// ---------------------------------------------------------------------------
__global__ void __launch_bounds__(256)
crf_gold_kernel(const float* __restrict__ feats,
                const int* __restrict__ tags,
                const float* __restrict__ trans,
                float* __restrict__ out) {
    const int tid  = threadIdx.x;
    const int lane = tid & 31;
    int gw   = (blockIdx.x * blockDim.x + tid) >> 5;
    int b    = gw >> 2;
    int seg  = gw & 3;

    const int*   tg  = tags  + (size_t)b * TLEN;
    const float* fbp = feats + (size_t)b * TLEN * KTAG;

    int t0 = seg * (TLEN / 4); if (seg == 0) t0 = 1;
    int t1 = (seg + 1) * (TLEN / 4);

    float s = 0.0f;
    for (int t = t0 + lane; t < t1; t += 32) {
        int ct = tg[t];
        int pt = tg[t - 1];
        s += trans[ct * KTAG + pt] + fbp[(size_t)t * KTAG + ct];
    }
#pragma unroll
    for (int o = 16; o > 0; o >>= 1)
        s += __shfl_xor_sync(0xffffffffu, s, o);
    if (lane == 0) g_goldp[gw] = s;

    // last-block reduction
    __threadfence();
    __shared__ int is_last;
    if (tid == 0) {
        int old = atomicAdd(&g_cnt, 1);
        is_last = (old == (int)gridDim.x - 1) ? 1 : 0;
    }
    __syncthreads();
    if (is_last) {
        __threadfence();
        __shared__ float sh[8];
        float acc = 0.0f;
        for (int x = tid; x < BTOT; x += 256) {
            float g = g_goldp[4 * x] + g_goldp[4 * x + 1] +
                      g_goldp[4 * x + 2] + g_goldp[4 * x + 3];
            acc += g_forward[x] - g;
        }
#pragma unroll
        for (int o = 16; o > 0; o >>= 1)
            acc += __shfl_xor_sync(0xffffffffu, acc, o);
        if (lane == 0) sh[tid >> 5] = acc;
        __syncthreads();
        if (tid == 0) {
            float tot = 0.0f;
#pragma unroll
            for (int k = 0; k < 8; k++) tot += sh[k];
            out[0] = tot / (float)BTOT;
            g_cnt  = 0;   // reset for next graph replay
        }
    }
}

extern "C" void kernel_launch(void* const* d_in, const int* in_sizes, int n_in,
                              void* d_out, int out_size) {
    const float* feats = (const float*)d_in[0];
    const int*   tags  = (const int*)d_in[1];
    const float* trans = (const float*)d_in[2];
    float* out = (float*)d_out;

    // forward first: ncu (-s 5 -c 1) lands on this kernel
    crf_forward_kernel<<<BTOT / 4, 128>>>(feats, trans);
    crf_gold_kernel<<<GOLD_GRID, 256>>>(feats, tags, trans, out);
}

// round 9
// speedup vs baseline: 1.7331x; 1.0465x over previous
#include <cuda_runtime.h>
#include <cstdint>

#define KTAG 64
#define BTOT 1024
#define TLEN 512
#define START_TAG 62
#define FWD_GRID (BTOT / 4)   // 256 blocks x 4 warps = 1024 rows

// Scratch (allocation-free rule: __device__ globals)
__device__ float g_res[BTOT];   // forward_score[b] - gold_score[b]
__device__ int   g_cnt = 0;

typedef unsigned long long ull;

__device__ __forceinline__ ull pk2(float x, float y) {
    return (ull)__float_as_uint(x) | ((ull)__float_as_uint(y) << 32);
}
__device__ __forceinline__ float lo2(ull v) { return __uint_as_float((unsigned)v); }
__device__ __forceinline__ float hi2(ull v) { return __uint_as_float((unsigned)(v >> 32)); }
__device__ __forceinline__ float rcpf(float x) {
    float r; asm("rcp.approx.f32 %0, %1;" : "=f"(r) : "f"(x)); return r;
}

#define FMA2(acc, a, b) asm("fma.rn.f32x2 %0, %1, %2, %0;" : "+l"(acc) : "l"(a), "l"(b))
#define ADD2(d, a, b)   asm("add.rn.f32x2 %0, %1, %2;" : "=l"(d) : "l"(a), "l"(b))
#define MUL2(d, a, b)   asm("mul.rn.f32x2 %0, %1, %2;" : "=l"(d) : "l"(a), "l"(b))

// ---------------------------------------------------------------------------
// Fully fused CRF kernel. One warp per batch row; lane l owns tags 2l, 2l+1
// and their E = exp(transitions) rows (f32x2-packed regs; the structurally
// zero pair (62,63) is skipped: w[62]==0 for t>=2 and E[:,63]==0).
// Per step: s_i = sum_j E[i,j] w_j (16 LDS.128 + 60 FMA2); w' = s * exp(f_t),
// renormalized by u = w[0] only every 4th step (exact bookkeeping; bounded
// growth keeps everything well inside fp32 range). feat pipeline is 4 deep
// (MLP=4). Gold path folded in: tags row cached in smem; feats[t][ct] is
// shuffled from the lane that already holds it; trans[ct,pt] hits L1.
// Final mean reduction via last-block pattern -> single kernel launch.
// ---------------------------------------------------------------------------
__global__ void __launch_bounds__(128, 2)
crf_fused_kernel(const float* __restrict__ feats,
                 const int* __restrict__ tags,
                 const float* __restrict__ trans,
                 float* __restrict__ out) {
    const int lane = threadIdx.x & 31;
    const int w    = threadIdx.x >> 5;          // row within CTA (0..3)
    const int b    = blockIdx.x * 4 + w;
    const int i0   = 2 * lane;
    const int i1   = 2 * lane + 1;

    __shared__ __align__(16) float sw_[4][2][KTAG];
    __shared__ __align__(16) int   stags[4][TLEN];

    // cache this row's tags (int4 coalesced)
    {
        const int4* tg4 = (const int4*)(tags + (size_t)b * TLEN);
        int4* st4 = (int4*)stags[w];
#pragma unroll
        for (int j = lane; j < TLEN / 4; j += 32) st4[j] = tg4[j];
    }

    // E rows for tags i0, i1 (f32x2 packed over j); pair jj=31 skipped
    ull E0[31], E1[31];
#pragma unroll
    for (int jj = 0; jj < 31; jj++) {
        E0[jj] = pk2(__expf(trans[i0 * KTAG + 2 * jj]),
                     __expf(trans[i0 * KTAG + 2 * jj + 1]));
        E1[jj] = pk2(__expf(trans[i1 * KTAG + 2 * jj]),
                     __expf(trans[i1 * KTAG + 2 * jj + 1]));
    }

    const float* fb = feats + (size_t)b * TLEN * KTAG;

    // t = 1 exact: w1 = exp(trans[:,START] + feat1)
    float2 f1 = *(const float2*)(fb + 1 * KTAG + i0);
    float a0 = trans[i0 * KTAG + START_TAG] + f1.x;
    float a1 = trans[i1 * KTAG + START_TAG] + f1.y;
    *(float2*)&sw_[w][0][i0] = make_float2(__expf(a0), __expf(a1));
    float L = 0.0f;
    __syncwarp();                                 // stags + w1 visible

    // gold init (t = 1): trans[ct,pt] + feats[1][ct] via shfl
    int   pt   = stags[w][0];
    float gold;
    {
        int ct = stags[w][1];
        float gs = (ct & 1) ? f1.y : f1.x;
        gold = trans[ct * KTAG + pt] + __shfl_sync(0xffffffffu, gs, ct >> 1);
        pt = ct;
    }

    // 4-deep feat pipeline: F[k] = feat(t = 2+k) raw
    float2 F[4];
#pragma unroll
    for (int k = 0; k < 4; k++)
        F[k] = *(const float2*)(fb + (size_t)(2 + k) * KTAG + i0);

    // gold accumulation for step T, raw feat pair (FX, FY)
#define GOLD_ACC(T, FX, FY)                                                   \
    {                                                                         \
        int ct = stags[w][(T)];                                               \
        float gs = (ct & 1) ? (FY) : (FX);                                    \
        gold += trans[ct * KTAG + pt];                                        \
        gold += __shfl_sync(0xffffffffu, gs, ct >> 1);                        \
        pt = ct;                                                              \
    }

    // one recurrence step; NORM = 1 -> renormalize by u = w[0]
#define STEP_BODY(T, EFC0, EFC1, NORM)                                        \
    {                                                                         \
        const int rbuf = (T) & 1;                                             \
        const ulonglong2* vp = (const ulonglong2*)sw_[w][rbuf];               \
        ulonglong2 v0 = vp[0];                                                \
        ull c0 = 0, c1 = 0, c2 = 0, c3 = 0;                                   \
        ull d0 = 0, d1 = 0, d2 = 0, d3 = 0;                                   \
        FMA2(c0, E0[0], v0.x); FMA2(c1, E0[1], v0.y);                         \
        FMA2(d0, E1[0], v0.x); FMA2(d1, E1[1], v0.y);                         \
        _Pragma("unroll")                                                     \
        for (int q = 1; q < 16; q++) {                                        \
            ulonglong2 vv = vp[q];                                            \
            if (q == 15) {            /* pair (62,63) contributes zero */     \
                FMA2(c2, E0[30], vv.x);                                       \
                FMA2(d2, E1[30], vv.x);                                       \
            } else if (q & 1) {                                               \
                FMA2(c2, E0[2 * q], vv.x); FMA2(c3, E0[2 * q + 1], vv.y);     \
                FMA2(d2, E1[2 * q], vv.x); FMA2(d3, E1[2 * q + 1], vv.y);     \
            } else {                                                          \
                FMA2(c0, E0[2 * q], vv.x); FMA2(c1, E0[2 * q + 1], vv.y);     \
                FMA2(d0, E1[2 * q], vv.x); FMA2(d1, E1[2 * q + 1], vv.y);     \
            }                                                                 \
        }                                                                     \
        ull cA, cB, cs, dA, dB, ds, wn;                                       \
        ADD2(cA, c0, c2); ADD2(cB, c1, c3); ADD2(cs, cA, cB);                 \
        ADD2(dA, d0, d2); ADD2(dB, d1, d3); ADD2(ds, dA, dB);                 \
        float s0 = lo2(cs) + hi2(cs);                                         \
        float s1 = lo2(ds) + hi2(ds);                                         \
        if (NORM) {                                                           \
            float uu = lo2(v0.x);                                             \
            float r  = rcpf(uu);                                              \
            L += __logf(uu);                                                  \
            MUL2(wn, pk2(s0, s1), pk2((EFC0) * r, (EFC1) * r));               \
        } else {                                                              \
            MUL2(wn, pk2(s0, s1), pk2((EFC0), (EFC1)));                       \
        }                                                                     \
        *(ull*)&sw_[w][rbuf ^ 1][i0] = wn;                                    \
        __syncwarp();                                                         \
    }

    // main loop: t = 2 .. 509, 127 blocks of 4 (MLP=4); norm at k == 3
    for (int kb = 0; kb < 127; kb++) {
#pragma unroll
        for (int k = 0; k < 4; k++) {
            const int t = 2 + 4 * kb + k;
            float fx = F[k].x, fy = F[k].y;
            GOLD_ACC(t, fx, fy)
            float efc0 = __expf(fx);
            float efc1 = __expf(fy);
            int tn = t + 4; if (tn > TLEN - 1) tn = TLEN - 1;
            F[k] = *(const float2*)(fb + (size_t)tn * KTAG + i0);
            if (k == 3) { STEP_BODY(t, efc0, efc1, 1) }
            else        { STEP_BODY(t, efc0, efc1, 0) }
        }
    }

    // t = 510 (feat in F[0])
    {
        float fx = F[0].x, fy = F[0].y;
        GOLD_ACC(510, fx, fy)
        float efc0 = __expf(fx);
        float efc1 = __expf(fy);
        STEP_BODY(510, efc0, efc1, 0)
    }

    // final step t = 511 (feat in F[1]): forward = L + log(sum_i s_i*exp(f_i))
    {
        float fx = F[1].x, fy = F[1].y;
        GOLD_ACC(511, fx, fy)
        float ef0 = __expf(fx);
        float ef1 = __expf(fy);
        const int rbuf = (TLEN - 1) & 1;
        const ulonglong2* vp = (const ulonglong2*)sw_[w][rbuf];
        ull c0 = 0, c1 = 0, c2 = 0, c3 = 0;
        ull d0 = 0, d1 = 0, d2 = 0, d3 = 0;
#pragma unroll
        for (int q = 0; q < 16; q++) {
            ulonglong2 vv = vp[q];
            if (q == 15) {
                FMA2(c2, E0[30], vv.x);
                FMA2(d2, E1[30], vv.x);
            } else if (q & 1) {
                FMA2(c2, E0[2 * q], vv.x); FMA2(c3, E0[2 * q + 1], vv.y);
                FMA2(d2, E1[2 * q], vv.x); FMA2(d3, E1[2 * q + 1], vv.y);
            } else {
                FMA2(c0, E0[2 * q], vv.x); FMA2(c1, E0[2 * q + 1], vv.y);
                FMA2(d0, E1[2 * q], vv.x); FMA2(d1, E1[2 * q + 1], vv.y);
            }
        }
        ull cA, cB, cs, dA, dB, ds;
        ADD2(cA, c0, c2); ADD2(cB, c1, c3); ADD2(cs, cA, cB);
        ADD2(dA, d0, d2); ADD2(dB, d1, d3); ADD2(ds, dA, dB);
        float s0 = lo2(cs) + hi2(cs);
        float s1 = lo2(ds) + hi2(ds);
        float z = s0 * ef0 + s1 * ef1;
#pragma unroll
        for (int o = 16; o > 0; o >>= 1)
            z += __shfl_xor_sync(0xffffffffu, z, o);
        if (lane == 0) g_res[b] = (L + __logf(z)) - gold;
    }
#undef STEP_BODY
#undef GOLD_ACC

    // ---- last-block mean reduction (deterministic order, counter resets) ----
    __threadfence();
    __shared__ int is_last;
    if (threadIdx.x == 0) {
        int old = atomicAdd(&g_cnt, 1);
        is_last = (old == FWD_GRID - 1) ? 1 : 0;
    }
    __syncthreads();
    if (is_last) {
        __threadfence();
        __shared__ float sh[4];
        const int tid = threadIdx.x;
        float acc = 0.0f;
        for (int x = tid; x < BTOT; x += 128) acc += g_res[x];
#pragma unroll
        for (int o = 16; o > 0; o >>= 1)
            acc += __shfl_xor_sync(0xffffffffu, acc, o);
        if ((tid & 31) == 0) sh[tid >> 5] = acc;
        __syncthreads();
        if (tid == 0) {
            out[0] = (sh[0] + sh[1] + sh[2] + sh[3]) / (float)BTOT;
            g_cnt  = 0;   // reset for next graph replay
        }
    }
}

extern "C" void kernel_launch(void* const* d_in, const int* in_sizes, int n_in,
                              void* d_out, int out_size) {
    const float* feats = (const float*)d_in[0];
    const int*   tags  = (const int*)d_in[1];
    const float* trans = (const float*)d_in[2];
    float* out = (float*)d_out;

    crf_fused_kernel<<<FWD_GRID, 128>>>(feats, tags, trans, out);
}